// round 14
// baseline (speedup 1.0000x reference)
#include <cuda_runtime.h>
#include <cuda_bf16.h>

// MedianFilter1D: x[16, 64, 16384] fp32, window k=9, zero padding.
// 1024 rows x 16384 = 2,097,152 chunks of 8 outputs.
//
// Round 14 — R13 (single-wave persistent, rolling double buffer; best dur
// 22.6us) with the loop unrolled by 2 so buffers A/B alternate roles
// structurally: removes the 8-float register copy + tightens the
// load-ahead distance to a full compute phase. fma pipe (reg-copy MOVs)
// 4.4% -> ~1%, recovered issue slots go to ALU/loads.
//
// Compute: sort 7 adjacent pairs; sorted-4 runs via 3-CE merge of sorted
// pairs; ranks 3,4 of each window-pair's shared 8 via pruned odd-even
// merge(4,4); median9 = clamp(inserted, s3, s4).

#define CE(a, b) { float _lo = fminf(a, b); float _hi = fmaxf(a, b); (a) = _lo; (b) = _hi; }

__device__ __forceinline__ void ld_in8(const float* p, float* v)
{
    asm volatile(
        "ld.global.nc.L2::evict_last.v8.f32 {%0,%1,%2,%3,%4,%5,%6,%7}, [%8];"
        : "=f"(v[0]), "=f"(v[1]), "=f"(v[2]), "=f"(v[3]),
          "=f"(v[4]), "=f"(v[5]), "=f"(v[6]), "=f"(v[7])
        : "l"(p));
}

__device__ __forceinline__ void st_out8(float* p, const float* o)
{
    asm volatile(
        "st.global.L2::evict_first.v8.f32 [%0], {%1,%2,%3,%4,%5,%6,%7,%8};"
        :: "l"(p),
           "f"(o[0]), "f"(o[1]), "f"(o[2]), "f"(o[3]),
           "f"(o[4]), "f"(o[5]), "f"(o[6]), "f"(o[7])
        : "memory");
}

static constexpr int L      = 16384;
static constexpr int ROWS   = 16 * 64;
static constexpr int TPB    = 256;
static constexpr int NCHUNK = ROWS * (L / 8);     // 2,097,152
static constexpr int GRID   = 148 * 6;            // 888 blocks, single wave
static constexpr int STRIDE = GRID * TPB;         // 227,328 threads

__device__ __forceinline__ void process_chunk(
    const float* __restrict__ x, float* __restrict__ y,
    const float* own, int c, int lane)
{
    const unsigned FULL = 0xFFFFFFFFu;
    float v[16];
    #pragma unroll
    for (int i = 0; i < 8; i++) v[4 + i] = own[i];

    // Halos from neighbor lanes (consecutive c across lanes).
    float4 lh, rh;
    lh.x = __shfl_up_sync(FULL, v[8],  1);
    lh.y = __shfl_up_sync(FULL, v[9],  1);
    lh.z = __shfl_up_sync(FULL, v[10], 1);
    lh.w = __shfl_up_sync(FULL, v[11], 1);
    rh.x = __shfl_down_sync(FULL, v[4], 1);
    rh.y = __shfl_down_sync(FULL, v[5], 1);
    rh.z = __shfl_down_sync(FULL, v[6], 1);
    rh.w = __shfl_down_sync(FULL, v[7], 1);

    int cm = c & 2047;   // chunk position within its row
    if (lane == 0) {
        if (cm != 0) lh = __ldg(reinterpret_cast<const float4*>(x + 8 * (size_t)c - 4));
        else         lh = make_float4(0.f, 0.f, 0.f, 0.f);
    }
    if (lane == 31) {
        if (cm != 2047) rh = __ldg(reinterpret_cast<const float4*>(x + 8 * (size_t)c + 8));
        else            rh = make_float4(0.f, 0.f, 0.f, 0.f);
    }
    v[0]  = lh.x; v[1]  = lh.y; v[2]  = lh.z; v[3]  = lh.w;
    v[12] = rh.x; v[13] = rh.y; v[14] = rh.z; v[15] = rh.w;

    // Sorted pairs P_j = sorted(v[2j+1], v[2j+2]), j = 0..6.
    float pl[7], ph[7];
    #pragma unroll
    for (int j = 0; j < 7; j++) {
        pl[j] = fminf(v[2*j + 1], v[2*j + 2]);
        ph[j] = fmaxf(v[2*j + 1], v[2*j + 2]);
    }

    // Runs R[i] = sorted-4 of v[2i+1 .. 2i+5) = merge(P_i, P_{i+1}), 3 CE.
    float R[6][4];
    #pragma unroll
    for (int i = 0; i < 6; i++) {
        float x0 = pl[i], x1 = ph[i], x2 = pl[i + 1], x3 = ph[i + 1];
        CE(x0, x2) CE(x1, x3) CE(x1, x2)
        R[i][0] = x0; R[i][1] = x1; R[i][2] = x2; R[i][3] = x3;
    }

    float o[8];
    #pragma unroll
    for (int j = 0; j < 4; j++) {
        int b = 2 * j;
        const float* A = R[j];       // sorted v[b+1 .. b+5)
        const float* B = R[j + 2];   // sorted v[b+5 .. b+9)
        float e2 = fmaxf(fmaxf(A[0], B[0]), fminf(A[2], B[2]));
        float o1 = fminf(fmaxf(A[1], B[1]), fminf(A[3], B[3]));
        float s3 = fminf(o1, e2);
        float s4 = fmaxf(o1, e2);
        o[b]     = fminf(fmaxf(v[b],     s3), s4);
        o[b + 1] = fminf(fmaxf(v[b + 9], s3), s4);
    }

    st_out8(y + 8 * (size_t)c, o);
}

__global__ __launch_bounds__(TPB, 6)
void median9_kernel(const float* __restrict__ x, float* __restrict__ y)
{
    int t    = blockIdx.x * TPB + threadIdx.x;
    int lane = threadIdx.x & 31;

    float A[8], B[8];
    int c = t;
    ld_in8(x + 8 * (size_t)c, A);          // prologue load into A

    // Unroll-2 rolling pipeline: buffers alternate roles, no register copy.
    #pragma unroll 1
    for (;;) {
        // --- phase A: compute from A, prefetch into B ---
        int cn = c + STRIDE;
        bool moreB = cn < NCHUNK;
        if (moreB) ld_in8(x + 8 * (size_t)cn, B);
        process_chunk(x, y, A, c, lane);
        if (!moreB) break;

        // --- phase B: compute from B, prefetch into A ---
        int cn2 = cn + STRIDE;
        bool moreA = cn2 < NCHUNK;
        if (moreA) ld_in8(x + 8 * (size_t)cn2, A);
        process_chunk(x, y, B, cn, lane);
        if (!moreA) break;

        c = cn2;
    }
}

extern "C" void kernel_launch(void* const* d_in, const int* in_sizes, int n_in,
                              void* d_out, int out_size)
{
    const float* x = (const float*)d_in[0];
    float* y = (float*)d_out;
    median9_kernel<<<GRID, TPB>>>(x, y);
}

// round 15
// speedup vs baseline: 1.3049x; 1.3049x over previous
#include <cuda_runtime.h>
#include <cuda_bf16.h>

// MedianFilter1D: x[16, 64, 16384] fp32, window k=9, zero padding.
// 1024 rows x 16384 = 2,097,152 chunks of 8 outputs.
//
// Round 15 — shfl-free persistent kernel. Issue-budget analysis of R13:
// ~130 warp-issues/chunk at issue 47%; SHFL halos + lane-edge guards + the
// rolling-buffer copy are ~25% of the stream and add a MIO latency chain
// between load and compute. Replace with R1-style direct overlapping loads:
//   left  halo float4 [cb-4, cb):  predicated (zero iff chunk at row start)
//   own   2x float4   [cb, cb+8):  unconditional
//   right halo float4 [cb+8,cb+12): predicated (zero iff chunk at row end)
// Uniform control flow, no shuffles. 2x L1 read amplification is free
// (L1 was 37%). Single-wave persistent: GRID = 148 SMs x 5 blocks,
// launch_bounds(256,5) (<=51 regs), rolling double buffer of 16 floats.
//
// Compute: sort 7 adjacent pairs; sorted-4 runs via 3-CE merge of sorted
// pairs; ranks 3,4 of each window-pair's shared 8 via pruned odd-even
// merge(4,4); median9 = clamp(inserted, s3, s4).

#define CE(a, b) { float _lo = fminf(a, b); float _hi = fmaxf(a, b); (a) = _lo; (b) = _hi; }

__device__ __forceinline__ void st_out8(float* p, const float* o)
{
    asm volatile(
        "st.global.L2::evict_first.v8.f32 [%0], {%1,%2,%3,%4,%5,%6,%7,%8};"
        :: "l"(p),
           "f"(o[0]), "f"(o[1]), "f"(o[2]), "f"(o[3]),
           "f"(o[4]), "f"(o[5]), "f"(o[6]), "f"(o[7])
        : "memory");
}

static constexpr int L      = 16384;
static constexpr int ROWS   = 16 * 64;
static constexpr int TPB    = 256;
static constexpr int NCHUNK = ROWS * (L / 8);     // 2,097,152
static constexpr int GRID   = 148 * 5;            // 740 blocks, single wave
static constexpr int STRIDE = GRID * TPB;         // 189,440 threads

// Load the 16-float window for chunk c into v[0..16): [8c-4, 8c+12).
__device__ __forceinline__ void load_window(const float* __restrict__ x, int c, float* v)
{
    const float4* p = reinterpret_cast<const float4*>(x + 8 * (size_t)c);
    int cm = c & 2047;                       // chunk position within row

    float4 a = __ldg(p);                     // [cb, cb+4)
    float4 b = __ldg(p + 1);                 // [cb+4, cb+8)
    float4 lh = (cm != 0)    ? __ldg(p - 1)  // [cb-4, cb)
                             : make_float4(0.f, 0.f, 0.f, 0.f);
    float4 rh = (cm != 2047) ? __ldg(p + 2)  // [cb+8, cb+12)
                             : make_float4(0.f, 0.f, 0.f, 0.f);

    v[0]  = lh.x; v[1]  = lh.y; v[2]  = lh.z; v[3]  = lh.w;
    v[4]  = a.x;  v[5]  = a.y;  v[6]  = a.z;  v[7]  = a.w;
    v[8]  = b.x;  v[9]  = b.y;  v[10] = b.z;  v[11] = b.w;
    v[12] = rh.x; v[13] = rh.y; v[14] = rh.z; v[15] = rh.w;
}

__device__ __forceinline__ void compute_store(
    float* __restrict__ y, const float* v, int c)
{
    // Sorted pairs P_j = sorted(v[2j+1], v[2j+2]), j = 0..6.
    float pl[7], ph[7];
    #pragma unroll
    for (int j = 0; j < 7; j++) {
        pl[j] = fminf(v[2*j + 1], v[2*j + 2]);
        ph[j] = fmaxf(v[2*j + 1], v[2*j + 2]);
    }

    // Runs R[i] = sorted-4 of v[2i+1 .. 2i+5) = merge(P_i, P_{i+1}), 3 CE.
    float R[6][4];
    #pragma unroll
    for (int i = 0; i < 6; i++) {
        float x0 = pl[i], x1 = ph[i], x2 = pl[i + 1], x3 = ph[i + 1];
        CE(x0, x2) CE(x1, x3) CE(x1, x2)
        R[i][0] = x0; R[i][1] = x1; R[i][2] = x2; R[i][3] = x3;
    }

    float o[8];
    #pragma unroll
    for (int j = 0; j < 4; j++) {
        int b = 2 * j;
        const float* A = R[j];       // sorted v[b+1 .. b+5)
        const float* B = R[j + 2];   // sorted v[b+5 .. b+9)
        float e2 = fmaxf(fmaxf(A[0], B[0]), fminf(A[2], B[2]));
        float o1 = fminf(fmaxf(A[1], B[1]), fminf(A[3], B[3]));
        float s3 = fminf(o1, e2);
        float s4 = fmaxf(o1, e2);
        o[b]     = fminf(fmaxf(v[b],     s3), s4);
        o[b + 1] = fminf(fmaxf(v[b + 9], s3), s4);
    }

    st_out8(y + 8 * (size_t)c, o);
}

__global__ __launch_bounds__(TPB, 5)
void median9_kernel(const float* __restrict__ x, float* __restrict__ y)
{
    int t = blockIdx.x * TPB + threadIdx.x;

    float A[16], B[16];
    int c = t;
    load_window(x, c, A);                    // prologue

    // Rolling pipeline: load c+STRIDE while computing c. ~11 iters/thread.
    #pragma unroll 1
    for (;;) {
        int cn = c + STRIDE;
        bool more = cn < NCHUNK;
        if (more) load_window(x, cn, B);
        compute_store(y, A, c);
        if (!more) break;
        c = cn;
        #pragma unroll
        for (int i = 0; i < 16; i++) A[i] = B[i];
    }
}

extern "C" void kernel_launch(void* const* d_in, const int* in_sizes, int n_in,
                              void* d_out, int out_size)
{
    const float* x = (const float*)d_in[0];
    float* y = (float*)d_out;
    median9_kernel<<<GRID, TPB>>>(x, y);
}